// round 1
// baseline (speedup 1.0000x reference)
#include <cuda_runtime.h>
#include <cstdint>

// Collapsed constants: {ta, tc, alpha/128, beta}
//   t2_q   = ta * x_q + tc            (log2-domain logit slope per query)
//   risk_b = (alpha/128) * sum_q m_q + beta
__device__ float g_c[4];

__device__ __forceinline__ float ex2f_fast(float x) {
    float y;
    asm("ex2.approx.ftz.f32 %0, %1;" : "=f"(y) : "f"(x));
    return y;
}

// One warp. Thread e (0..31) owns feature column e.
__global__ void precompute_kernel(const float* __restrict__ Wt, const float* __restrict__ bt,
                                  const float* __restrict__ Wq, const float* __restrict__ bq,
                                  const float* __restrict__ Wk, const float* __restrict__ bk,
                                  const float* __restrict__ Wv, const float* __restrict__ bv,
                                  const float* __restrict__ Wo, const float* __restrict__ bo) {
    const int e = threadIdx.x;  // 0..31
    float qv = 0.f, kv = 0.f, vv = 0.f, qb = 0.f, vb = 0.f;
#pragma unroll
    for (int d = 0; d < 32; d++) {
        const float wt  = Wt[d];
        const float btd = bt[d];
        const float wq = Wq[d * 32 + e];
        const float wk = Wk[d * 32 + e];
        const float wv = Wv[d * 32 + e];
        qv = fmaf(wt,  wq, qv);
        kv = fmaf(wt,  wk, kv);
        vv = fmaf(wt,  wv, vv);
        qb = fmaf(btd, wq, qb);
        vb = fmaf(btd, wv, vb);
    }
    qb += bq[e];
    vb += bv[e];
    const float wo = Wo[e];  // Wo is (32,1)

    float a  = qv * kv;   // logit slope coefficient
    float c1 = qb * kv;   // logit offset coefficient
    float al = vv * wo;   // alpha partial
    float be = vb * wo;   // beta partial
#pragma unroll
    for (int off = 16; off > 0; off >>= 1) {
        a  += __shfl_xor_sync(0xffffffffu, a,  off);
        c1 += __shfl_xor_sync(0xffffffffu, c1, off);
        al += __shfl_xor_sync(0xffffffffu, al, off);
        be += __shfl_xor_sync(0xffffffffu, be, off);
    }
    if (e == 0) {
        const float LOG2E = 1.4426950408889634f;
        const float INV_SQRT_D = 0.17677669529663687f;  // 1/sqrt(32)
        g_c[0] = a  * INV_SQRT_D * LOG2E;
        g_c[1] = c1 * INV_SQRT_D * LOG2E;
        g_c[2] = al * (1.0f / 128.0f);
        g_c[3] = be + bo[0];
    }
}

// One warp per batch row; 8 warps (8 batches) per 256-thread block.
// Lane L owns queries q = 4L..4L+3 (its own float4 of x). x row broadcast via smem.
__global__ __launch_bounds__(256) void attn_collapsed_kernel(const float* __restrict__ x,
                                                             float* __restrict__ out,
                                                             int B) {
    __shared__ float sx[8][128];
    const int warp = threadIdx.x >> 5;
    const int lane = threadIdx.x & 31;
    const int b = blockIdx.x * 8 + warp;
    if (b >= B) return;

    const float ta = g_c[0];
    const float tc = g_c[1];

    // Coalesced load of this batch's 128 x values: lane L gets x[4L..4L+3]
    const float4 xv = reinterpret_cast<const float4*>(x + (size_t)b * 128)[lane];
    float* s = sx[warp];
    reinterpret_cast<float4*>(s)[lane] = xv;

    // Row max/min for softmax stabilization (exact cancellation-safe)
    float mx = fmaxf(fmaxf(xv.x, xv.y), fmaxf(xv.z, xv.w));
    float mn = fminf(fminf(xv.x, xv.y), fminf(xv.z, xv.w));
#pragma unroll
    for (int off = 16; off > 0; off >>= 1) {
        mx = fmaxf(mx, __shfl_xor_sync(0xffffffffu, mx, off));
        mn = fminf(mn, __shfl_xor_sync(0xffffffffu, mn, off));
    }
    __syncwarp();

    // Per-query log2-domain slopes and negated stabilizers
    float t0 = fmaf(ta, xv.x, tc);
    float t1 = fmaf(ta, xv.y, tc);
    float t2 = fmaf(ta, xv.z, tc);
    float t3 = fmaf(ta, xv.w, tc);
    float nm0 = -((t0 > 0.f) ? t0 * mx : t0 * mn);
    float nm1 = -((t1 > 0.f) ? t1 * mx : t1 * mn);
    float nm2 = -((t2 > 0.f) ? t2 * mx : t2 * mn);
    float nm3 = -((t3 > 0.f) ? t3 * mx : t3 * mn);

    float se0 = 0.f, se1 = 0.f, se2 = 0.f, se3 = 0.f;
    float sx0 = 0.f, sx1 = 0.f, sx2 = 0.f, sx3 = 0.f;

#pragma unroll 8
    for (int k = 0; k < 128; k++) {
        const float xk = s[k];  // warp-broadcast LDS
        const float e0 = ex2f_fast(fmaf(t0, xk, nm0));
        const float e1 = ex2f_fast(fmaf(t1, xk, nm1));
        const float e2 = ex2f_fast(fmaf(t2, xk, nm2));
        const float e3 = ex2f_fast(fmaf(t3, xk, nm3));
        se0 += e0; sx0 = fmaf(xk, e0, sx0);
        se1 += e1; sx1 = fmaf(xk, e1, sx1);
        se2 += e2; sx2 = fmaf(xk, e2, sx2);
        se3 += e3; sx3 = fmaf(xk, e3, sx3);
    }

    // m_q = (sum x*e) / (sum e); then sum the 4 local queries
    float msum = __fdividef(sx0, se0) + __fdividef(sx1, se1)
               + __fdividef(sx2, se2) + __fdividef(sx3, se3);
#pragma unroll
    for (int off = 16; off > 0; off >>= 1)
        msum += __shfl_xor_sync(0xffffffffu, msum, off);

    if (lane == 0)
        out[b] = fmaf(g_c[2], msum, g_c[3]);
}

extern "C" void kernel_launch(void* const* d_in, const int* in_sizes, int n_in,
                              void* d_out, int out_size) {
    const float* x  = (const float*)d_in[0];
    const float* Wt = (const float*)d_in[1];
    const float* bt = (const float*)d_in[2];
    const float* Wq = (const float*)d_in[3];
    const float* bq = (const float*)d_in[4];
    const float* Wk = (const float*)d_in[5];
    const float* bk = (const float*)d_in[6];
    const float* Wv = (const float*)d_in[7];
    const float* bv = (const float*)d_in[8];
    const float* Wo = (const float*)d_in[9];
    const float* bo = (const float*)d_in[10];
    float* out = (float*)d_out;

    const int B = in_sizes[0] / 128;

    precompute_kernel<<<1, 32>>>(Wt, bt, Wq, bq, Wk, bk, Wv, bv, Wo, bo);
    attn_collapsed_kernel<<<(B + 7) / 8, 256>>>(x, out, B);
}

// round 2
// speedup vs baseline: 1.2453x; 1.2453x over previous
#include <cuda_runtime.h>
#include <cstdint>

typedef unsigned long long u64;

__device__ __forceinline__ float ex2f(float x) {
    float y;
    asm("ex2.approx.ftz.f32 %0, %1;" : "=f"(y) : "f"(x));
    return y;
}
__device__ __forceinline__ u64 pk2(float lo, float hi) {
    u64 r; asm("mov.b64 %0, {%1, %2};" : "=l"(r) : "f"(lo), "f"(hi)); return r;
}
__device__ __forceinline__ void upk2(float& lo, float& hi, u64 v) {
    asm("mov.b64 {%0, %1}, %2;" : "=f"(lo), "=f"(hi) : "l"(v));
}
__device__ __forceinline__ u64 pk2i(unsigned lo, unsigned hi) {
    u64 r; asm("mov.b64 %0, {%1, %2};" : "=l"(r) : "r"(lo), "r"(hi)); return r;
}
__device__ __forceinline__ void upk2i(unsigned& lo, unsigned& hi, u64 v) {
    asm("mov.b64 {%0, %1}, %2;" : "=r"(lo), "=r"(hi) : "l"(v));
}
__device__ __forceinline__ u64 f2fma(u64 a, u64 b, u64 c) {
    u64 r; asm("fma.rn.f32x2 %0, %1, %2, %3;" : "=l"(r) : "l"(a), "l"(b), "l"(c)); return r;
}
__device__ __forceinline__ u64 f2add(u64 a, u64 b) {
    u64 r; asm("add.rn.f32x2 %0, %1, %2;" : "=l"(r) : "l"(a), "l"(b)); return r;
}

// Fused kernel: warp 0 of each block folds the weights into 4 scalars
// (L2-served redundant work), then 1 warp = 1 batch row, 8 rows/block.
// Queries q0..q2 use MUFU ex2; q3 uses an FMA-pipe packed-f32x2 exp2
// (magic-constant range reduction + deg-4 Taylor + ALU exponent injection).
__global__ __launch_bounds__(256) void attn_fused_kernel(
    const float* __restrict__ x, float* __restrict__ out, int B,
    const float* __restrict__ Wt, const float* __restrict__ bt,
    const float* __restrict__ Wq, const float* __restrict__ bq,
    const float* __restrict__ Wk, const float* __restrict__ bk,
    const float* __restrict__ Wv, const float* __restrict__ bv,
    const float* __restrict__ Wo, const float* __restrict__ bo) {
    __shared__ float sx[8][128];
    __shared__ float sc[4];

    const int warp = threadIdx.x >> 5;
    const int lane = threadIdx.x & 31;
    const int b = blockIdx.x * 8 + warp;
    const bool active = (b < B);

    float4 xv = make_float4(0.f, 0.f, 0.f, 0.f);
    if (active) {
        xv = reinterpret_cast<const float4*>(x + (size_t)b * 128)[lane];
        reinterpret_cast<float4*>(sx[warp])[lane] = xv;
    }

    // ---- per-block weight collapse (warp 0) ----
    if (warp == 0) {
        const int e = lane;
        float qv = 0.f, kv = 0.f, vv = 0.f, qb = 0.f, vb = 0.f;
#pragma unroll
        for (int d = 0; d < 32; d++) {
            const float wt  = Wt[d];
            const float btd = bt[d];
            qv = fmaf(wt,  Wq[d * 32 + e], qv);
            kv = fmaf(wt,  Wk[d * 32 + e], kv);
            vv = fmaf(wt,  Wv[d * 32 + e], vv);
            qb = fmaf(btd, Wq[d * 32 + e], qb);
            vb = fmaf(btd, Wv[d * 32 + e], vb);
        }
        qb += bq[e];
        vb += bv[e];
        const float wo = Wo[e];
        float a  = qv * kv;
        float c1 = qb * kv;
        float al = vv * wo;
        float be = vb * wo;
#pragma unroll
        for (int off = 16; off > 0; off >>= 1) {
            a  += __shfl_xor_sync(0xffffffffu, a,  off);
            c1 += __shfl_xor_sync(0xffffffffu, c1, off);
            al += __shfl_xor_sync(0xffffffffu, al, off);
            be += __shfl_xor_sync(0xffffffffu, be, off);
        }
        if (e == 0) {
            const float LOG2E = 1.4426950408889634f;
            const float INV_SQRT_D = 0.17677669529663687f;
            sc[0] = a  * INV_SQRT_D * LOG2E;
            sc[1] = c1 * INV_SQRT_D * LOG2E;
            sc[2] = al * (1.0f / 128.0f);
            sc[3] = be + bo[0];
        }
    }
    __syncthreads();
    if (!active) return;

    const float ta = sc[0];
    const float tc = sc[1];

    // row max/min for exact-cancellation-safe stabilization
    float mx = fmaxf(fmaxf(xv.x, xv.y), fmaxf(xv.z, xv.w));
    float mn = fminf(fminf(xv.x, xv.y), fminf(xv.z, xv.w));
#pragma unroll
    for (int off = 16; off > 0; off >>= 1) {
        mx = fmaxf(mx, __shfl_xor_sync(0xffffffffu, mx, off));
        mn = fminf(mn, __shfl_xor_sync(0xffffffffu, mn, off));
    }
    __syncwarp();

    const float t0 = fmaf(ta, xv.x, tc);
    const float t1 = fmaf(ta, xv.y, tc);
    const float t2 = fmaf(ta, xv.z, tc);
    const float t3 = fmaf(ta, xv.w, tc);
    const float nm0 = -((t0 > 0.f) ? t0 * mx : t0 * mn);
    const float nm1 = -((t1 > 0.f) ? t1 * mx : t1 * mn);
    const float nm2 = -((t2 > 0.f) ? t2 * mx : t2 * mn);
    const float nm3 = -((t3 > 0.f) ? t3 * mx : t3 * mn);

    // packed poly constants (2^f, deg-4 Taylor; |f|<=0.5 -> rel err ~5e-5)
    const float MAGIC = 12582912.0f;  // 1.5 * 2^23
    const u64 MP   = pk2(MAGIC, MAGIC);
    const u64 NMP  = pk2(-MAGIC, -MAGIC);
    const u64 N1P  = pk2(-1.0f, -1.0f);
    const u64 C4   = pk2(0.00961813f, 0.00961813f);
    const u64 C3   = pk2(0.05550411f, 0.05550411f);
    const u64 C2   = pk2(0.24022651f, 0.24022651f);
    const u64 C1   = pk2(0.69314718f, 0.69314718f);
    const u64 ONE  = pk2(1.0f, 1.0f);

    u64 se0 = 0ull, se1 = 0ull, se2 = 0ull, se3 = 0ull;
    u64 sa0 = 0ull, sa1 = 0ull, sa2 = 0ull, sa3 = 0ull;

    const float* s = sx[warp];

#pragma unroll 4
    for (int k = 0; k < 128; k += 2) {
        const float2 xk2 = *reinterpret_cast<const float2*>(s + k);  // LDS.64 broadcast
        const u64 xkp = pk2(xk2.x, xk2.y);

        // q0..q2 via MUFU
        {
            const float ea = ex2f(fmaf(t0, xk2.x, nm0));
            const float eb = ex2f(fmaf(t0, xk2.y, nm0));
            const u64 ep = pk2(ea, eb);
            se0 = f2add(se0, ep);
            sa0 = f2fma(xkp, ep, sa0);
        }
        {
            const float ea = ex2f(fmaf(t1, xk2.x, nm1));
            const float eb = ex2f(fmaf(t1, xk2.y, nm1));
            const u64 ep = pk2(ea, eb);
            se1 = f2add(se1, ep);
            sa1 = f2fma(xkp, ep, sa1);
        }
        {
            const float ea = ex2f(fmaf(t2, xk2.x, nm2));
            const float eb = ex2f(fmaf(t2, xk2.y, nm2));
            const u64 ep = pk2(ea, eb);
            se2 = f2add(se2, ep);
            sa2 = f2fma(xkp, ep, sa2);
        }
        // q3 via FMA-pipe packed exp2 (z <= 0 by construction; clamp guards
        // the exponent-injection wraparound for extreme negatives)
        {
            const float za = fmaxf(fmaf(t3, xk2.x, nm3), -120.f);
            const float zb = fmaxf(fmaf(t3, xk2.y, nm3), -120.f);
            const u64 zp = pk2(za, zb);
            const u64 tp = f2add(zp, MP);       // round-to-nearest-int in mantissa
            const u64 hp = f2add(tp, NMP);      // h = round(z)
            const u64 fp = f2fma(hp, N1P, zp);  // f = z - h, |f| <= 0.5
            u64 pp = f2fma(C4, fp, C3);
            pp = f2fma(pp, fp, C2);
            pp = f2fma(pp, fp, C1);
            pp = f2fma(pp, fp, ONE);
            unsigned tl, th, pl, ph;
            upk2i(tl, th, tp);
            upk2i(pl, ph, pp);
            const unsigned el = pl + (tl << 23);   // 2^n scale via exponent add
            const unsigned eh = ph + (th << 23);
            const u64 ep = pk2i(el, eh);
            se3 = f2add(se3, ep);
            sa3 = f2fma(xkp, ep, sa3);
        }
    }

    float lo, hi;
    upk2(lo, hi, se0); const float S0 = lo + hi;
    upk2(lo, hi, sa0); const float A0 = lo + hi;
    upk2(lo, hi, se1); const float S1 = lo + hi;
    upk2(lo, hi, sa1); const float A1 = lo + hi;
    upk2(lo, hi, se2); const float S2 = lo + hi;
    upk2(lo, hi, sa2); const float A2 = lo + hi;
    upk2(lo, hi, se3); const float S3 = lo + hi;
    upk2(lo, hi, sa3); const float A3 = lo + hi;

    float msum = __fdividef(A0, S0) + __fdividef(A1, S1)
               + __fdividef(A2, S2) + __fdividef(A3, S3);
#pragma unroll
    for (int off = 16; off > 0; off >>= 1)
        msum += __shfl_xor_sync(0xffffffffu, msum, off);

    if (lane == 0)
        out[b] = fmaf(sc[2], msum, sc[3]);
}

extern "C" void kernel_launch(void* const* d_in, const int* in_sizes, int n_in,
                              void* d_out, int out_size) {
    const float* x  = (const float*)d_in[0];
    const float* Wt = (const float*)d_in[1];
    const float* bt = (const float*)d_in[2];
    const float* Wq = (const float*)d_in[3];
    const float* bq = (const float*)d_in[4];
    const float* Wk = (const float*)d_in[5];
    const float* bk = (const float*)d_in[6];
    const float* Wv = (const float*)d_in[7];
    const float* bv = (const float*)d_in[8];
    const float* Wo = (const float*)d_in[9];
    const float* bo = (const float*)d_in[10];
    float* out = (float*)d_out;

    const int B = in_sizes[0] / 128;
    (void)bk;  // cancels exactly in softmax

    attn_fused_kernel<<<(B + 7) / 8, 256>>>(x, out, B,
                                            Wt, bt, Wq, bq, Wk, bk, Wv, bv, Wo, bo);
}